// round 5
// baseline (speedup 1.0000x reference)
#include <cuda_runtime.h>
#include <cstddef>

// Shape fixed by dataset: target [B=32, T=4, N=512] f32
// Output: source [B, 2, N, N] f32  (+ optional target pass-through tail)
#define BN    512
#define BT    4
#define BB    32
#define NMASK 511
#define KT    8       // k-rows per block
#define LV    2       // l-values per thread
#define TPB   256     // TPB*LV == BN
#define SRC_ELEMS (BB * 2 * BN * BN)

__device__ float2 g_y[BB * BT * BN];   // per-(b,t) spectra scratch

typedef unsigned long long u64;

// ---- packed f32x2 helpers (ptxas only emits FFMA2 via explicit PTX) ----
__device__ __forceinline__ u64 pack2(float lo, float hi) {
    u64 r; asm("mov.b64 %0, {%1, %2};" : "=l"(r) : "f"(lo), "f"(hi)); return r;
}
__device__ __forceinline__ void unpack2(u64 v, float& lo, float& hi) {
    asm("mov.b64 {%0, %1}, %2;" : "=f"(lo), "=f"(hi) : "l"(v));
}
__device__ __forceinline__ u64 mul2(u64 a, u64 b) {
    u64 d; asm("mul.rn.f32x2 %0, %1, %2;" : "=l"(d) : "l"(a), "l"(b)); return d;
}
__device__ __forceinline__ void fma2(u64& d, u64 a, u64 b) {
    asm("fma.rn.f32x2 %0, %1, %2, %0;" : "+l"(d) : "l"(a), "l"(b));
}
__device__ __forceinline__ float negf(float x) {
    return __int_as_float(__float_as_int(x) ^ 0x80000000);  // XOR on alu pipe
}

// ---------------------------------------------------------------------------
// Two-stage DFT (N = 512 = 8 x 64), in-block twiddles, fused tail copy.
// ---------------------------------------------------------------------------
__global__ void dft_kernel(const float* __restrict__ x,
                           float* __restrict__ out, int out_size) {
    __shared__ float  sx[BN];
    __shared__ float2 stw[BN];
    __shared__ float2 sz[BN];

    const int row = blockIdx.x;        // 0..127 = b*BT + t
    const int tid = threadIdx.x;

    sx[tid] = x[(size_t)row * BN + tid];
    {
        float s, c;
        sincospif(-(float)tid * (1.0f / 256.0f), &s, &c);
        stw[tid] = make_float2(c, s);
    }
    __syncthreads();

    {   // Stage B: Z[b][r]
        const int b = tid >> 3;
        const int r = tid & 7;
        float zr = 0.f, zi = 0.f;
#pragma unroll
        for (int a = 0; a < 8; a++) {
            float  xv = sx[64 * a + b];
            float2 w  = stw[(64 * r * a) & NMASK];
            zr = fmaf(xv, w.x, zr);
            zi = fmaf(xv, w.y, zi);
        }
        sz[tid] = make_float2(zr, zi);
    }
    __syncthreads();

    {   // Stage C: y[k] = sum_b W^{kb} Z[b][k&7]
        const int k = tid;
        const int r = k & 7;
        float ar = 0.f, ai = 0.f;
        int idx = 0;
#pragma unroll 8
        for (int b = 0; b < 64; b++) {
            float2 w = stw[idx];
            float2 z = sz[b * 8 + r];
            ar = fmaf(w.x, z.x, fmaf(-w.y, z.y, ar));
            ai = fmaf(w.x, z.y, fmaf( w.y, z.x, ai));
            idx = (idx + k) & NMASK;
        }
        g_y[(size_t)row * BN + k] = make_float2(ar, ai);
    }

    {   // fused tail pass-through
        size_t o = (size_t)SRC_ELEMS + (size_t)row * BN + tid;
        if (o < (size_t)out_size) out[o] = sx[tid];
    }
}

// ---------------------------------------------------------------------------
// Bispectrum, full compute (all stores coalesced), packed f32x2 math.
//   Bx[k,l] = y[k] * conj(y[l]) * y[(l-k)&511], mean over t.
// Block: 256 threads, KT=8 k-rows, thread owns l0=2*tid (LV=2 columns).
// Per t, the thread's y[(l-k)] needs form ONE contiguous 10-wide window
// (indices b0..b0+9 mod 512, b0 = l0-k0-8, 16B-aligned) -> 5 LDS.128.
// ---------------------------------------------------------------------------
__global__ void __launch_bounds__(TPB) bispec_kernel(float* __restrict__ out) {
    __shared__ float2 sy[BT][BN];      // 16 KB

    const int b   = blockIdx.y;
    const int k0  = blockIdx.x * KT;
    const int tid = threadIdx.x;
    const int l0  = tid * LV;

#pragma unroll
    for (int t = 0; t < BT; t++)
#pragma unroll
        for (int i = tid; i < BN; i += TPB)
            sy[t][i] = g_y[((size_t)b * BT + t) * BN + i];
    __syncthreads();

    u64 acc[KT][LV];
#pragma unroll
    for (int kk = 0; kk < KT; kk++)
#pragma unroll
        for (int j = 0; j < LV; j++) acc[kk][j] = 0ull;

    const int b0 = (l0 - k0 - 8) & NMASK;   // even -> 16B-aligned float4 loads

#pragma unroll
    for (int t = 0; t < BT; t++) {
        // contiguous m-window w[0..9] ~ sy[t][(b0+i)&511]
        float wx[10], wy[10];
#pragma unroll
        for (int j = 0; j < 5; j++) {
            float4 v = *reinterpret_cast<const float4*>(&sy[t][(b0 + 2 * j) & NMASK]);
            wx[2 * j]     = v.x; wy[2 * j]     = v.y;
            wx[2 * j + 1] = v.z; wy[2 * j + 1] = v.w;
        }
        // yl pair (l0, l0+1), duplicated lanes for f32x2
        float4 ylv = *reinterpret_cast<const float4*>(&sy[t][l0]);
        u64 Dlr[LV], Dli[LV];
        Dlr[0] = pack2(ylv.x, ylv.x);  Dli[0] = pack2(ylv.y, ylv.y);
        Dlr[1] = pack2(ylv.z, ylv.z);  Dli[1] = pack2(ylv.w, ylv.w);

#pragma unroll
        for (int kk = 0; kk < KT; kk++) {
            float2 yk = sy[t][k0 + kk];             // warp-broadcast LDS
            u64 Yk  = pack2(yk.x, yk.y);
            u64 Ykn = pack2(yk.y, negf(yk.x));
#pragma unroll
            for (int j = 0; j < LV; j++) {
                // P = y[k]*conj(y[l]) = (pr,pi)
                u64 P = mul2(Yk, Dlr[j]);
                fma2(P, Ykn, Dli[j]);
                float pr, pi; unpack2(P, pr, pi);
                u64 Pn = pack2(negf(pi), pr);       // (-pi, pr)
                const int widx = 8 + j - kk;        // in [1,9], compile-time
                u64 Dmx = pack2(wx[widx], wx[widx]);
                u64 Dmy = pack2(wy[widx], wy[widx]);
                // (Ar,Ai) += (mx,mx)*(pr,pi) + (my,my)*(-pi,pr)
                fma2(acc[kk][j], Dmx, P);
                fma2(acc[kk][j], Dmy, Pn);
            }
        }
    }

    float* outb = out + (size_t)b * 2 * BN * BN;
#pragma unroll
    for (int kk = 0; kk < KT; kk++) {
        float a0r, a0i, a1r, a1i;
        unpack2(acc[kk][0], a0r, a0i);
        unpack2(acc[kk][1], a1r, a1i);
        const size_t k = (size_t)(k0 + kk);
        *reinterpret_cast<float2*>(&outb[k * BN + l0]) =
            make_float2(a0r * 0.25f, a1r * 0.25f);
        *reinterpret_cast<float2*>(&outb[(size_t)BN * BN + k * BN + l0]) =
            make_float2(a0i * 0.25f, a1i * 0.25f);
    }
}

extern "C" void kernel_launch(void* const* d_in, const int* in_sizes, int n_in,
                              void* d_out, int out_size) {
    const float* x   = (const float*)d_in[0];
    float*       out = (float*)d_out;

    dft_kernel<<<BB * BT, BN>>>(x, out, out_size);
    bispec_kernel<<<dim3(BN / KT, BB), TPB>>>(out);
}

// round 8
// speedup vs baseline: 1.1994x; 1.1994x over previous
#include <cuda_runtime.h>
#include <cstddef>

// Shape fixed by dataset: target [B=32, T=4, N=512] f32
// Output: source [B, 2, N, N] f32  (+ optional target pass-through tail)
#define BN    512
#define BT    4
#define BB    32
#define NMASK 511
#define TS    32               // square tile side
#define NT    (BN / TS)        // 16 tiles per dim
#define NPAIR (NT * (NT + 1) / 2)   // 136 upper-triangle tile pairs
#define SRC_ELEMS (BB * 2 * BN * BN)

__device__ float2 g_y[BB * BT * BN];   // per-(b,t) spectra scratch

// ---------------------------------------------------------------------------
// Two-stage DFT (N = 512 = 8 x 64), in-block twiddles, fused tail copy.
// ---------------------------------------------------------------------------
__global__ void dft_kernel(const float* __restrict__ x,
                           float* __restrict__ out, int out_size) {
    __shared__ float  sx[BN];
    __shared__ float2 stw[BN];
    __shared__ float2 sz[BN];

    const int row = blockIdx.x;        // 0..127 = b*BT + t
    const int tid = threadIdx.x;

    sx[tid] = x[(size_t)row * BN + tid];
    {
        float s, c;
        sincospif(-(float)tid * (1.0f / 256.0f), &s, &c);
        stw[tid] = make_float2(c, s);
    }
    __syncthreads();

    {   // Stage B: Z[b][r]
        const int b = tid >> 3;
        const int r = tid & 7;
        float zr = 0.f, zi = 0.f;
#pragma unroll
        for (int a = 0; a < 8; a++) {
            float  xv = sx[64 * a + b];
            float2 w  = stw[(64 * r * a) & NMASK];
            zr = fmaf(xv, w.x, zr);
            zi = fmaf(xv, w.y, zi);
        }
        sz[tid] = make_float2(zr, zi);
    }
    __syncthreads();

    {   // Stage C: y[k] = sum_b W^{kb} Z[b][k&7]
        const int k = tid;
        const int r = k & 7;
        float ar = 0.f, ai = 0.f;
        int idx = 0;
#pragma unroll 8
        for (int b = 0; b < 64; b++) {
            float2 w = stw[idx];
            float2 z = sz[b * 8 + r];
            ar = fmaf(w.x, z.x, fmaf(-w.y, z.y, ar));
            ai = fmaf(w.x, z.y, fmaf( w.y, z.x, ai));
            idx = (idx + k) & NMASK;
        }
        g_y[(size_t)row * BN + k] = make_float2(ar, ai);
    }

    {   // fused tail pass-through (target copy), if present in output
        size_t o = (size_t)SRC_ELEMS + (size_t)row * BN + tid;
        if (o < (size_t)out_size) out[o] = sx[tid];
    }
}

// ---------------------------------------------------------------------------
// Bispectrum via Hermitian square-tile pairs.
//   Bx[k,l] = y[k]*conj(y[l])*y[(l-k)&511], mean over t;
//   real input => Bx[l,k] = conj(Bx[k,l]).
// Block handles tile pair (I,J), I<=J: computes T[32x32] at rows k=I*32+i,
// cols l=J*32+j ONCE; writes it directly (coalesced rows) and, for I!=J,
// writes the (J,I) tile as conj(T^t) via a shared-memory transpose so the
// mirror stores are also full coalesced rows. Coverage exact & disjoint.
// Block: 256 threads; thread (tx = l-offset, ty) owns k-offsets ty*4..ty*4+3.
// ---------------------------------------------------------------------------
__global__ void __launch_bounds__(256) bispec_kernel(float* __restrict__ out) {
    __shared__ float2 sy[BT][BN];      // 16 KB; reused as transpose staging

    const int b = blockIdx.y;

    // decode pair index -> (I, J), I <= J
    int p = blockIdx.x, I = 0;
    while (p >= NT - I) { p -= NT - I; I++; }
    const int J = I + p;

    const int tid = threadIdx.x;
    const int tx  = tid & 31;          // l within tile
    const int ty  = tid >> 5;          // k group (4 rows each)

#pragma unroll
    for (int t = 0; t < BT; t++)
        for (int i = tid; i < BN; i += 256)
            sy[t][i] = g_y[((size_t)b * BT + t) * BN + i];
    __syncthreads();

    const int l     = J * TS + tx;
    const int kbase = I * TS + ty * 4;

    float ar[4] = {0.f, 0.f, 0.f, 0.f};
    float ai[4] = {0.f, 0.f, 0.f, 0.f};

#pragma unroll
    for (int t = 0; t < BT; t++) {
        float2 yl = sy[t][l];
#pragma unroll
        for (int q = 0; q < 4; q++) {
            float2 yk = sy[t][kbase + q];                 // broadcast
            float2 ym = sy[t][(l - kbase - q) & NMASK];   // consecutive/lane
            // p = y[k] * conj(y[l])
            float pr = fmaf(yk.x, yl.x,  yk.y * yl.y);
            float pi = fmaf(yk.y, yl.x, -yk.x * yl.y);
            // acc += p * y[m]
            ar[q] = fmaf(pr, ym.x, fmaf(-pi, ym.y, ar[q]));
            ai[q] = fmaf(pr, ym.y, fmaf( pi, ym.x, ai[q]));
        }
    }
#pragma unroll
    for (int q = 0; q < 4; q++) { ar[q] *= 0.25f; ai[q] *= 0.25f; }

    float* outb = out + (size_t)b * 2 * BN * BN;

    // Direct tile: rows kbase+q, col l -> 128B coalesced per warp
#pragma unroll
    for (int q = 0; q < 4; q++) {
        outb[(size_t)(kbase + q) * BN + l]                   = ar[q];
        outb[(size_t)BN * BN + (size_t)(kbase + q) * BN + l] = ai[q];
    }

    if (I != J) {
        __syncthreads();               // all sy reads complete
        float2* st = &sy[0][0];        // reuse as 32x33 staging (8.4 KB)

        // transpose write: st[j][i] with j = tx, i = ty*4+q
#pragma unroll
        for (int q = 0; q < 4; q++)
            st[tx * 33 + (ty * 4 + q)] = make_float2(ar[q], ai[q]);
        __syncthreads();

        // mirror tile (J,I): row j' = ty*4+q, cols I*32+tx (coalesced)
#pragma unroll
        for (int q = 0; q < 4; q++) {
            float2 v = st[(ty * 4 + q) * 33 + tx];
            const size_t row = (size_t)(J * TS + ty * 4 + q);
            outb[row * BN + I * TS + tx]                   =  v.x;
            outb[(size_t)BN * BN + row * BN + I * TS + tx] = -v.y;
        }
    }
}

extern "C" void kernel_launch(void* const* d_in, const int* in_sizes, int n_in,
                              void* d_out, int out_size) {
    const float* x   = (const float*)d_in[0];
    float*       out = (float*)d_out;

    dft_kernel<<<BB * BT, BN>>>(x, out, out_size);
    bispec_kernel<<<dim3(NPAIR, BB), 256>>>(out);
}

// round 13
// speedup vs baseline: 1.4905x; 1.2427x over previous
#include <cuda_runtime.h>
#include <cstddef>

// Shape fixed by dataset: target [B=32, T=4, N=512] f32
// Output: source [B, 2, N, N] f32  (+ optional target pass-through tail)
#define BN    512
#define BT    4
#define BB    32
#define NMASK 511
#define TS    32
#define NT    (BN / TS)             // 16
#define NPAIR (NT * (NT + 1) / 2)   // 136
#define PP    8                     // tile pairs per block
#define NBLKX (NPAIR / PP)          // 17
#define SRC_ELEMS (BB * 2 * BN * BN)

// Packed spectra: g_yp[0][b*BN+k] = (y_t0.re, y_t0.im, y_t1.re, y_t1.im)
//                 g_yp[1][...]    = (y_t2, y_t3)
__device__ float4 g_yp[2][BB * BN];   // 512 KB total

// ---------------------------------------------------------------------------
// Two-stage DFT (N = 512 = 8 x 64), in-block twiddles, packed store,
// fused target pass-through tail.
// ---------------------------------------------------------------------------
__global__ void dft_kernel(const float* __restrict__ x,
                           float* __restrict__ out, int out_size) {
    __shared__ float  sx[BN];
    __shared__ float2 stw[BN];
    __shared__ float2 sz[BN];

    const int row = blockIdx.x;        // 0..127 = b*BT + t
    const int tid = threadIdx.x;

    sx[tid] = x[(size_t)row * BN + tid];
    {
        float s, c;
        sincospif(-(float)tid * (1.0f / 256.0f), &s, &c);
        stw[tid] = make_float2(c, s);
    }
    __syncthreads();

    {   // Stage B: Z[b][r]
        const int bb = tid >> 3;
        const int r  = tid & 7;
        float zr = 0.f, zi = 0.f;
#pragma unroll
        for (int a = 0; a < 8; a++) {
            float  xv = sx[64 * a + bb];
            float2 w  = stw[(64 * r * a) & NMASK];
            zr = fmaf(xv, w.x, zr);
            zi = fmaf(xv, w.y, zi);
        }
        sz[tid] = make_float2(zr, zi);
    }
    __syncthreads();

    {   // Stage C: y[k] = sum_b W^{kb} Z[b][k&7]
        const int k = tid;
        const int r = k & 7;
        float ar = 0.f, ai = 0.f;
        int idx = 0;
#pragma unroll 8
        for (int bb = 0; bb < 64; bb++) {
            float2 w = stw[idx];
            float2 z = sz[bb * 8 + r];
            ar = fmaf(w.x, z.x, fmaf(-w.y, z.y, ar));
            ai = fmaf(w.x, z.y, fmaf( w.y, z.x, ai));
            idx = (idx + k) & NMASK;
        }
        const int b    = row >> 2;
        const int t    = row & 3;
        float2* dst = reinterpret_cast<float2*>(&g_yp[t >> 1][b * BN + k]) + (t & 1);
        *dst = make_float2(ar, ai);
    }

    {   // fused tail pass-through (target copy), if present in output
        size_t o = (size_t)SRC_ELEMS + (size_t)row * BN + tid;
        if (o < (size_t)out_size) out[o] = sx[tid];
    }
}

// ---------------------------------------------------------------------------
// Bispectrum via Hermitian tile pairs, t-packed LDS.128, persistent blocks.
//   Bx[k,l] = y[k]*conj(y[l])*y[(l-k)&511], mean over t;
//   real input => Bx[l,k] = conj(Bx[k,l]).
// Grid (17, 32): each block loads the 4 packed spectra once (16 KB) and
// processes PP=8 consecutive tile pairs (I,J), I<=J. Direct tile stores are
// coalesced rows; mirror tile (J,I) goes through a shared transpose so its
// stores are coalesced rows too. Coverage exact & disjoint.
// ---------------------------------------------------------------------------
__global__ void __launch_bounds__(256) bispec_kernel(float* __restrict__ out) {
    __shared__ float4 sy01[BN];        // (t0, t1) spectra, 8 KB
    __shared__ float4 sy23[BN];        // (t2, t3) spectra, 8 KB
    __shared__ float2 st[TS * 33];     // transpose staging, 8.25 KB

    const int b   = blockIdx.y;
    const int tid = threadIdx.x;
    const int tx  = tid & 31;          // l within tile
    const int ty  = tid >> 5;          // k group (4 rows)

    for (int i = tid; i < BN; i += 256) {
        sy01[i] = g_yp[0][b * BN + i];
        sy23[i] = g_yp[1][b * BN + i];
    }
    __syncthreads();

    float* outb = out + (size_t)b * 2 * BN * BN;

    // decode first pair index -> (I, J), I <= J (row-major upper triangle)
    int rem = blockIdx.x * PP, I = 0;
    while (rem >= NT - I) { rem -= NT - I; I++; }
    int J = I + rem;

    for (int pp = 0; pp < PP; pp++) {
        const int l  = J * TS + tx;
        const int kb = I * TS + ty * 4;
        const float4 yl01 = sy01[l];
        const float4 yl23 = sy23[l];
        const int base = l - kb;

        float ar[4] = {0.f, 0.f, 0.f, 0.f};
        float ai[4] = {0.f, 0.f, 0.f, 0.f};

#pragma unroll
        for (int q = 0; q < 4; q++) {
            const float4 yk01 = sy01[kb + q];          // broadcast
            const float4 yk23 = sy23[kb + q];
            const int m = (base - q) & NMASK;
            const float4 ym01 = sy01[m];               // consecutive/lane
            const float4 ym23 = sy23[m];
            {   // t0
                float pr = fmaf(yk01.x, yl01.x,  yk01.y * yl01.y);
                float pi = fmaf(yk01.y, yl01.x, -yk01.x * yl01.y);
                ar[q] = fmaf(pr, ym01.x, fmaf(-pi, ym01.y, ar[q]));
                ai[q] = fmaf(pr, ym01.y, fmaf( pi, ym01.x, ai[q]));
            }
            {   // t1
                float pr = fmaf(yk01.z, yl01.z,  yk01.w * yl01.w);
                float pi = fmaf(yk01.w, yl01.z, -yk01.z * yl01.w);
                ar[q] = fmaf(pr, ym01.z, fmaf(-pi, ym01.w, ar[q]));
                ai[q] = fmaf(pr, ym01.w, fmaf( pi, ym01.z, ai[q]));
            }
            {   // t2
                float pr = fmaf(yk23.x, yl23.x,  yk23.y * yl23.y);
                float pi = fmaf(yk23.y, yl23.x, -yk23.x * yl23.y);
                ar[q] = fmaf(pr, ym23.x, fmaf(-pi, ym23.y, ar[q]));
                ai[q] = fmaf(pr, ym23.y, fmaf( pi, ym23.x, ai[q]));
            }
            {   // t3
                float pr = fmaf(yk23.z, yl23.z,  yk23.w * yl23.w);
                float pi = fmaf(yk23.w, yl23.z, -yk23.z * yl23.w);
                ar[q] = fmaf(pr, ym23.z, fmaf(-pi, ym23.w, ar[q]));
                ai[q] = fmaf(pr, ym23.w, fmaf( pi, ym23.z, ai[q]));
            }
        }
#pragma unroll
        for (int q = 0; q < 4; q++) { ar[q] *= 0.25f; ai[q] *= 0.25f; }

        // Direct tile: rows kb+q, col l -> coalesced rows
#pragma unroll
        for (int q = 0; q < 4; q++) {
            outb[(size_t)(kb + q) * BN + l]                   = ar[q];
            outb[(size_t)BN * BN + (size_t)(kb + q) * BN + l] = ai[q];
        }

        if (I != J) {
            __syncthreads();           // st safe to overwrite (prev pair done)
#pragma unroll
            for (int q = 0; q < 4; q++)
                st[tx * 33 + ty * 4 + q] = make_float2(ar[q], ai[q]);
            __syncthreads();
            // Mirror tile (J,I): conj transpose, coalesced rows
#pragma unroll
            for (int q = 0; q < 4; q++) {
                float2 v = st[(ty * 4 + q) * 33 + tx];
                const size_t row = (size_t)(J * TS + ty * 4 + q);
                outb[row * BN + I * TS + tx]                   =  v.x;
                outb[(size_t)BN * BN + row * BN + I * TS + tx] = -v.y;
            }
        }

        if (++J == NT) { ++I; J = I; } // next pair in triangle order
    }
}

extern "C" void kernel_launch(void* const* d_in, const int* in_sizes, int n_in,
                              void* d_out, int out_size) {
    const float* x   = (const float*)d_in[0];
    float*       out = (float*)d_out;

    dft_kernel<<<BB * BT, BN>>>(x, out, out_size);
    bispec_kernel<<<dim3(NBLKX, BB), 256>>>(out);
}